// round 2
// baseline (speedup 1.0000x reference)
#include <cuda_runtime.h>
#include <cuda_bf16.h>

// Problem constants (fixed by dataset):
//   walk:  int32 [B=1024, L=80]
//   neg:   int32 [B=1024, A=76, NEG=4]
//   embed: f32   [1000000, D=128]
//   out:   f32 scalar = (sum softplus(-pos_logit) + sum softplus(neg_logit)) / (B*A*8)
#define L_WALK 80
#define W_WIN  5
#define A_ANC  (L_WALK - W_WIN + 1)   // 76
#define NNEG   4
#define DIM    128
#define NVEC   (DIM / 4)              // 32 float4 per row
#define NTHREADS 256
#define NWARPS   (NTHREADS / 32)

static __global__ void zero_kernel(float* out) {
    if (threadIdx.x == 0) out[0] = 0.0f;
}

__device__ __forceinline__ float warp_reduce_sum(float v) {
    v += __shfl_xor_sync(0xffffffffu, v, 16);
    v += __shfl_xor_sync(0xffffffffu, v, 8);
    v += __shfl_xor_sync(0xffffffffu, v, 4);
    v += __shfl_xor_sync(0xffffffffu, v, 2);
    v += __shfl_xor_sync(0xffffffffu, v, 1);
    return v;
}

// softplus(x) = max(x,0) + log(1 + exp(-|x|)); fast-math variants are
// accurate to ~1e-7 absolute here, far inside the 1e-3 rel-err budget.
__device__ __forceinline__ float softplus_f(float x) {
    return fmaxf(x, 0.0f) + __logf(1.0f + __expf(-fabsf(x)));
}

__global__ __launch_bounds__(NTHREADS, 1)
void sgns_kernel(const int* __restrict__ walk,
                 const int* __restrict__ neg,
                 const float* __restrict__ embed,
                 float* __restrict__ out,
                 float inv_total) {
    __shared__ float4 srow[L_WALK][NVEC];   // 80 x 128 f32 = 40 KB
    __shared__ int    swalk[L_WALK];
    __shared__ float  wsum[NWARPS];

    const int b    = blockIdx.x;
    const int tid  = threadIdx.x;
    const int lane = tid & 31;
    const int wid  = tid >> 5;

    if (tid < L_WALK) swalk[tid] = walk[(size_t)b * L_WALK + tid];
    __syncthreads();

    // Stage all 80 walk-row embeddings into shared memory (coalesced 512B rows).
    for (int r = wid; r < L_WALK; r += NWARPS) {
        const float4* src = (const float4*)(embed + (size_t)swalk[r] * DIM);
        srow[r][lane] = __ldg(src + lane);
    }
    __syncthreads();

    float acc = 0.0f;   // meaningful in lane 0 only

    // One warp per anchor; warps stride over the 76 anchors.
    for (int a = wid; a < A_ANC; a += NWARPS) {
        const float4 va = srow[a][lane];

        // Positive contexts: walk[a+1 .. a+4], already in smem.
        #pragma unroll
        for (int j = 1; j < W_WIN; j++) {
            const float4 vc = srow[a + j][lane];
            float d = va.x * vc.x + va.y * vc.y + va.z * vc.z + va.w * vc.w;
            d = warp_reduce_sum(d);
            if (lane == 0) acc += softplus_f(-d);
        }

        // Negative samples: 4 random gathers, issued together for MLP.
        const int* nrow = neg + ((size_t)b * A_ANC + a) * NNEG;
        const int i0 = nrow[0], i1 = nrow[1], i2 = nrow[2], i3 = nrow[3];
        const float4 v0 = __ldg((const float4*)(embed + (size_t)i0 * DIM) + lane);
        const float4 v1 = __ldg((const float4*)(embed + (size_t)i1 * DIM) + lane);
        const float4 v2 = __ldg((const float4*)(embed + (size_t)i2 * DIM) + lane);
        const float4 v3 = __ldg((const float4*)(embed + (size_t)i3 * DIM) + lane);

        float d0 = va.x * v0.x + va.y * v0.y + va.z * v0.z + va.w * v0.w;
        float d1 = va.x * v1.x + va.y * v1.y + va.z * v1.z + va.w * v1.w;
        float d2 = va.x * v2.x + va.y * v2.y + va.z * v2.z + va.w * v2.w;
        float d3 = va.x * v3.x + va.y * v3.y + va.z * v3.z + va.w * v3.w;
        d0 = warp_reduce_sum(d0);
        d1 = warp_reduce_sum(d1);
        d2 = warp_reduce_sum(d2);
        d3 = warp_reduce_sum(d3);
        if (lane == 0) {
            acc += softplus_f(d0) + softplus_f(d1) + softplus_f(d2) + softplus_f(d3);
        }
    }

    if (lane == 0) wsum[wid] = acc;
    __syncthreads();

    if (tid == 0) {
        float s = 0.0f;
        #pragma unroll
        for (int i = 0; i < NWARPS; i++) s += wsum[i];
        atomicAdd(out, s * inv_total);
    }
}

extern "C" void kernel_launch(void* const* d_in, const int* in_sizes, int n_in,
                              void* d_out, int out_size) {
    const int*   walk  = (const int*)d_in[0];
    const int*   neg   = (const int*)d_in[1];
    const float* embed = (const float*)d_in[2];
    float*       out   = (float*)d_out;

    const int B = in_sizes[0] / L_WALK;                 // 1024
    const float inv_total = 1.0f / ((float)B * A_ANC * (W_WIN - 1 + NNEG));

    zero_kernel<<<1, 32>>>(out);
    sgns_kernel<<<B, NTHREADS>>>(walk, neg, embed, out, inv_total);
}

// round 4
// speedup vs baseline: 1.7754x; 1.7754x over previous
#include <cuda_runtime.h>
#include <cuda_bf16.h>

// Problem constants (fixed by dataset):
//   walk:  int32 [B=1024, L=80]
//   neg:   int32 [B=1024, A=76, NEG=4]
//   embed: f32   [1000000, D=128]
//   out:   f32 scalar = (sum softplus(-pos) + sum softplus(neg)) / (B*A*8)
#define L_WALK   80
#define W_WIN    5
#define A_ANC    (L_WALK - W_WIN + 1)     // 76
#define NNEG     4
#define DIM      128
#define NVEC     (DIM / 4)                // 32 float4 per row
#define NTHREADS 256
#define NWARPS   (NTHREADS / 32)

#define SPLIT    2
#define ANC_PER  (A_ANC / SPLIT)          // 38 anchors per block
#define ROWS_PER (ANC_PER + W_WIN - 1)    // 42 walk rows staged per block

static __global__ void zero_kernel(float* out) {
    if (threadIdx.x == 0) out[0] = 0.0f;
}

__device__ __forceinline__ float warp_reduce_sum(float v) {
    v += __shfl_xor_sync(0xffffffffu, v, 16);
    v += __shfl_xor_sync(0xffffffffu, v, 8);
    v += __shfl_xor_sync(0xffffffffu, v, 4);
    v += __shfl_xor_sync(0xffffffffu, v, 2);
    v += __shfl_xor_sync(0xffffffffu, v, 1);
    return v;
}

// Pairwise combining reduce: lanes with (lane & off)==0 end up holding the
// a-reduction, lanes with the bit set hold the b-reduction.
__device__ __forceinline__ float cmb(float a, float b, int off, int lane) {
    float send = (lane & off) ? a : b;
    float keep = (lane & off) ? b : a;
    return keep + __shfl_xor_sync(0xffffffffu, send, off);
}

// softplus(x) = max(x,0) + log(1 + exp(-|x|)); fast-math variants are
// accurate to ~1e-7 absolute here, far inside the 1e-3 rel-err budget.
__device__ __forceinline__ float softplus_f(float x) {
    return fmaxf(x, 0.0f) + __logf(1.0f + __expf(-fabsf(x)));
}

__device__ __forceinline__ float dot4(float4 a, float4 b) {
    return a.x * b.x + a.y * b.y + a.z * b.z + a.w * b.w;
}

__global__ __launch_bounds__(NTHREADS, 8)
void sgns_kernel(const int* __restrict__ walk,
                 const int* __restrict__ neg,
                 const float* __restrict__ embed,
                 float* __restrict__ out,
                 float inv_total) {
    __shared__ float4 srow[ROWS_PER][NVEC];   // 42 x 512B = 21.5 KB
    __shared__ int    swalk[ROWS_PER];
    __shared__ int    sneg[ANC_PER * NNEG];   // 152 ints
    __shared__ float  wsum[NWARPS];

    const int bid  = blockIdx.x;
    const int wb   = bid >> 1;                // walk index
    const int base = (bid & 1) * ANC_PER;     // first anchor of this half
    const int tid  = threadIdx.x;
    const int lane = tid & 31;
    const int wid  = tid >> 5;

    if (tid < ROWS_PER)
        swalk[tid] = walk[(size_t)wb * L_WALK + base + tid];
    if (tid < ANC_PER * NNEG)
        sneg[tid] = neg[((size_t)wb * A_ANC + base) * NNEG + tid];
    __syncthreads();

    // Stage the 42 walk-row embeddings into shared memory (coalesced 512B rows).
    for (int r = wid; r < ROWS_PER; r += NWARPS) {
        const float4* src = (const float4*)(embed + (size_t)swalk[r] * DIM);
        srow[r][lane] = __ldg(src + lane);
    }
    __syncthreads();

    float acc = 0.0f;   // per-lane partial (8 softplus lanes contribute)

    // One warp per anchor; warps stride over the 38 anchors of this half.
    for (int a = wid; a < ANC_PER; a += NWARPS) {
        // Issue the 4 random gathers first so DRAM latency overlaps pos work.
        const int i0 = sneg[a * NNEG + 0];
        const int i1 = sneg[a * NNEG + 1];
        const int i2 = sneg[a * NNEG + 2];
        const int i3 = sneg[a * NNEG + 3];
        const float4 v0 = __ldg((const float4*)(embed + (size_t)i0 * DIM) + lane);
        const float4 v1 = __ldg((const float4*)(embed + (size_t)i1 * DIM) + lane);
        const float4 v2 = __ldg((const float4*)(embed + (size_t)i2 * DIM) + lane);
        const float4 v3 = __ldg((const float4*)(embed + (size_t)i3 * DIM) + lane);

        const float4 va = srow[a][lane];

        // Positive contexts (smem, reused 5x per row).
        const float p0 = dot4(va, srow[a + 1][lane]);
        const float p1 = dot4(va, srow[a + 2][lane]);
        const float p2 = dot4(va, srow[a + 3][lane]);
        const float p3 = dot4(va, srow[a + 4][lane]);

        // Negative dots (consume the in-flight gathers).
        const float p4 = dot4(va, v0);
        const float p5 = dot4(va, v1);
        const float p6 = dot4(va, v2);
        const float p7 = dot4(va, v3);

        // Multi-value warp reduction: 9 shfls reduce all 8 dots.
        // After this, lane bit4 of the lane id selects pos(0)/neg(1) group:
        //   bit16 -> pos vs neg, bits {8,4} -> which of the 4 within group.
        float r10 = cmb(p0, p4, 16, lane);
        float r11 = cmb(p1, p5, 16, lane);
        float r12 = cmb(p2, p6, 16, lane);
        float r13 = cmb(p3, p7, 16, lane);
        float q0  = cmb(r10, r11, 8, lane);
        float q1  = cmb(r12, r13, 8, lane);
        float r   = cmb(q0, q1, 4, lane);
        r += __shfl_xor_sync(0xffffffffu, r, 2);
        r += __shfl_xor_sync(0xffffffffu, r, 1);

        // Lanes 0,4,8,...,28 each hold one of the 8 full dot products.
        // bit16 set => negative-sample logit (softplus(+x)), else softplus(-x).
        if ((lane & 3) == 0) {
            const float x = (lane & 16) ? r : -r;
            acc += softplus_f(x);
        }
    }

    acc = warp_reduce_sum(acc);
    if (lane == 0) wsum[wid] = acc;
    __syncthreads();

    if (tid == 0) {
        float s = 0.0f;
        #pragma unroll
        for (int i = 0; i < NWARPS; i++) s += wsum[i];
        atomicAdd(out, s * inv_total);
    }
}

extern "C" void kernel_launch(void* const* d_in, const int* in_sizes, int n_in,
                              void* d_out, int out_size) {
    const int*   walk  = (const int*)d_in[0];
    const int*   neg   = (const int*)d_in[1];
    const float* embed = (const float*)d_in[2];
    float*       out   = (float*)d_out;

    const int B = in_sizes[0] / L_WALK;                 // 1024
    const float inv_total = 1.0f / ((float)B * A_ANC * (W_WIN - 1 + NNEG));

    zero_kernel<<<1, 32>>>(out);
    sgns_kernel<<<B * SPLIT, NTHREADS>>>(walk, neg, embed, out, inv_total);
}